// round 16
// baseline (speedup 1.0000x reference)
#include <cuda_runtime.h>

// DPLSafePolicy fused skinny GEMM (16384x2048 @ 2048x13) + softmax/ProbLog epilogue.
// R10 resubmit (R14 bench was an infra failure - container died, kernel never ran).
// R8's output-partitioned lanes (zero weight duplication) with a per-lane tiled
// weight layout that is delivery-optimal: lane stride 36 floats (144B) so each
// LDS.128 resolves in the mandatory 4 payload phases with no bank excess.
// Key model (validated R7 vs R9): L1 cost = RF delivery payload (512B/LDS.128,
// broadcast does NOT help). Payload/chunk: 426KB -> 256KB. One 896-thread CTA/SM
// (144KB weight tile + scratch), 28 warps, 4144 warps >= 4096 chunks single pass.

#define GRIDX 148
#define NTHR 896               // 28 warps, 1 CTA/SM, 72-reg cap
#define HDIM 2048
#define NROWS 16384
#define RPC 4
#define NCHUNK (NROWS / RPC)   // 4096
#define STAGE_F 1152           // 32 lanes * 36 floats per 64-col stage
#define WTILE_F (32 * STAGE_F) // 36864 floats = 144KB
#define SCRATCH_PW 56          // 4 rows x 14 floats per warp
#define SMEM_FLOATS (WTILE_F + (NTHR / 32) * SCRATCH_PW)
#define SMEM_BYTES (SMEM_FLOATS * 4)

typedef unsigned long long u64;

__device__ __forceinline__ u64 fma2(u64 a, u64 b, u64 c) {
    u64 d; asm("fma.rn.f32x2 %0, %1, %2, %3;" : "=l"(d) : "l"(a), "l"(b), "l"(c)); return d;
}
__device__ __forceinline__ void unpack2(u64 a, float& lo, float& hi) {
    asm("mov.b64 {%0, %1}, %2;" : "=f"(lo), "=f"(hi) : "l"(a));
}
__device__ __forceinline__ void pf_l2(const float* p) {
    asm volatile("prefetch.global.L2 [%0];" :: "l"(p));
}

__global__ void __launch_bounds__(NTHR, 1) policy_kernel(
    const float* __restrict__ x,
    const float* __restrict__ Wg, const float* __restrict__ bg,
    const float* __restrict__ Wp, const float* __restrict__ bp,
    const float* __restrict__ Wa, const float* __restrict__ ba,
    float* __restrict__ out)
{
    extern __shared__ float sw[];
    float* sred = sw + WTILE_F;
    const int tid = threadIdx.x;

    // ---- Pack per-lane weight tiles ----
    // Tile element (stage, l, q, i): l=(o,g)=(l&3, l>>2), k=q>>1, half=q&1.
    // plane = min(4o+k, 12); col = stage*64 + g*8 + half*4 + i.
    // dst = stage*1152 + l*36 + q*4 + i  (lane stride 36 floats = conflict-free phases)
    for (int grp = tid; grp < 32 * 32 * 8; grp += NTHR) {
        int stage = grp >> 8, rem = grp & 255;
        int l = rem >> 3, q = rem & 7;
        int o = l & 3, g = l >> 2, k = q >> 1, half = q & 1;
        int plane = min(4 * o + k, 12);
        int colbase = (stage << 6) + (g << 3) + (half << 2);
        float* dst = sw + stage * STAGE_F + l * 36 + q * 4;
#pragma unroll
        for (int i = 0; i < 4; i++) {
            int col = colbase + i;
            float v;
            if (plane < 4)      v = Wg[col * 4 + plane];
            else if (plane < 8) v = Wp[col * 4 + (plane - 4)];
            else                v = Wa[col * 5 + (plane - 8)];
            dst[i] = v;
        }
    }
    __syncthreads();

    const int warp = tid >> 5, lane = tid & 31;
    const int chunk = warp * GRIDX + blockIdx.x;   // interleaved over SMs
    if (chunk >= NCHUNK) return;

    const int o = lane & 3;           // output group: planes 4o..4o+3 (clamped to 12)
    const int g = lane >> 2;          // 8-col slice within each 64-col stage
    const int r0 = chunk * RPC;
    const float* xrow = x + (size_t)r0 * HDIM + (g << 3);
    const float* wlane = sw + lane * 36;

    u64 acc[4][4];   // [k][row]
#pragma unroll
    for (int k = 0; k < 4; k++)
#pragma unroll
        for (int r = 0; r < 4; r++) acc[k][r] = 0;

    // L2 prefetch pattern: lanes 0..7 cover 8 distinct lines (4 rows x 2 halves)
    const int pfrow = lane & 3, pfhalf = (lane >> 2) & 1;
    const float* pfb = x + (size_t)(r0 + pfrow) * HDIM + pfhalf * 32;

#pragma unroll 1
    for (int ss = 0; ss < 32; ss++) {
        const int xoff = ss << 6;
        if (ss < 30) pf_l2(pfb + xoff + 128);   // 2 stages ahead

        // x: 4 rows x 8 cols as K-pairs (8 LDG.128, o-quad same-address)
        double2 x0a = *(const double2*)(xrow + xoff);
        double2 x0b = *(const double2*)(xrow + xoff + 4);
        double2 x1a = *(const double2*)(xrow + HDIM + xoff);
        double2 x1b = *(const double2*)(xrow + HDIM + xoff + 4);
        double2 x2a = *(const double2*)(xrow + 2 * HDIM + xoff);
        double2 x2b = *(const double2*)(xrow + 2 * HDIM + xoff + 4);
        double2 x3a = *(const double2*)(xrow + 3 * HDIM + xoff);
        double2 x3b = *(const double2*)(xrow + 3 * HDIM + xoff + 4);
        u64 xp[4][4];
        xp[0][0] = __double_as_longlong(x0a.x); xp[0][1] = __double_as_longlong(x0a.y);
        xp[0][2] = __double_as_longlong(x0b.x); xp[0][3] = __double_as_longlong(x0b.y);
        xp[1][0] = __double_as_longlong(x1a.x); xp[1][1] = __double_as_longlong(x1a.y);
        xp[1][2] = __double_as_longlong(x1b.x); xp[1][3] = __double_as_longlong(x1b.y);
        xp[2][0] = __double_as_longlong(x2a.x); xp[2][1] = __double_as_longlong(x2a.y);
        xp[2][2] = __double_as_longlong(x2b.x); xp[2][3] = __double_as_longlong(x2b.y);
        xp[3][0] = __double_as_longlong(x3a.x); xp[3][1] = __double_as_longlong(x3a.y);
        xp[3][2] = __double_as_longlong(x3b.x); xp[3][3] = __double_as_longlong(x3b.y);

        const float* wst = wlane + ss * STAGE_F;
#define KSTEP(k) { \
            double2 w0 = *(const double2*)(wst + 8 * (k)); \
            double2 w1 = *(const double2*)(wst + 8 * (k) + 4); \
            u64 wa = __double_as_longlong(w0.x), wb_ = __double_as_longlong(w0.y); \
            u64 wc = __double_as_longlong(w1.x), wd = __double_as_longlong(w1.y); \
            _Pragma("unroll") \
            for (int r = 0; r < 4; r++) { \
                u64 a = acc[k][r]; \
                a = fma2(xp[r][0], wa, a); a = fma2(xp[r][1], wb_, a); \
                a = fma2(xp[r][2], wc, a); a = fma2(xp[r][3], wd, a); \
                acc[k][r] = a; \
            } \
        }
        KSTEP(0); KSTEP(1); KSTEP(2); KSTEP(3);
#undef KSTEP
    }

    // horizontal even+odd, then reduce over g (lane bits 2,3,4)
    float v[4][4];   // [row][k]
#pragma unroll
    for (int k = 0; k < 4; k++)
#pragma unroll
        for (int r = 0; r < 4; r++) {
            float lo, hi; unpack2(acc[k][r], lo, hi); v[r][k] = lo + hi;
        }
#pragma unroll
    for (int off = 4; off <= 16; off <<= 1)
#pragma unroll
        for (int r = 0; r < 4; r++)
#pragma unroll
            for (int k = 0; k < 4; k++)
                v[r][k] += __shfl_xor_sync(0xffffffffu, v[r][k], off);

    // g==0 lanes publish their 4 outputs per row to warp scratch
    float* red = sred + warp * SCRATCH_PW;
    if (g == 0) {
#pragma unroll
        for (int r = 0; r < 4; r++)
#pragma unroll
            for (int k = 0; k < 4; k++) {
                int j = 4 * o + k;
                if (j <= 12) red[r * 14 + j] = v[r][k];
            }
    }
    __syncwarp();

    if (lane < 4) {
        const int row = r0 + lane;
        const float* rv = red + lane * 14;
        float l0 = rv[0] + bg[0], l1 = rv[1] + bg[1], l2 = rv[2] + bg[2], l3 = rv[3] + bg[3];
        float mg = fmaxf(fmaxf(l0, l1), fmaxf(l2, l3));
        float eg0 = __expf(l0 - mg), eg1 = __expf(l1 - mg), eg2 = __expf(l2 - mg), eg3 = __expf(l3 - mg);
        float sg = eg0 + eg1 + eg2 + eg3;
        float p0 = rv[4] + bp[0], p1 = rv[5] + bp[1], p2 = rv[6] + bp[2], p3 = rv[7] + bp[3];
        float mp = fmaxf(fmaxf(p0, p1), fmaxf(p2, p3));
        float ep0 = __expf(p0 - mp), ep1 = __expf(p1 - mp), ep2 = __expf(p2 - mp), ep3 = __expf(p3 - mp);
        float sp = ep0 + ep1 + ep2 + ep3;
        float q0 = rv[8] + ba[0], q1 = rv[9] + ba[1], q2 = rv[10] + ba[2], q3 = rv[11] + ba[3], q4 = rv[12] + ba[4];
        float ma = fmaxf(fmaxf(fmaxf(q0, q1), fmaxf(q2, q3)), q4);
        float ea0 = __expf(q0 - ma), ea1 = __expf(q1 - ma), ea2 = __expf(q2 - ma),
              ea3 = __expf(q3 - ma), ea4 = __expf(q4 - ma);
        float t0 = ep0 * eg0 + ep1 * eg1 + ep2 * eg2 + ep3 * eg3;  // stay
        float t1 = ep0 * eg1 + ep2 * eg3;                           // up
        float t2 = ep1 * eg0 + ep3 * eg2;                           // down
        float inv = 1.0f / (sg * sp);
        float j0 = ea0 * (1.0f - t0 * inv);
        float j1 = ea1 * (1.0f - t1 * inv);
        float j2 = ea2 * (1.0f - t2 * inv);
        float s = j0 + j1 + j2 + ea3 + ea4;
        float is = 1.0f / s;
        float* oo = out + (size_t)row * 5;
        oo[0] = j0 * is; oo[1] = j1 * is; oo[2] = j2 * is; oo[3] = ea3 * is; oo[4] = ea4 * is;
    }
}

extern "C" void kernel_launch(void* const* d_in, const int* in_sizes, int n_in,
                              void* d_out, int out_size)
{
    const float* x  = (const float*)d_in[0];
    const float* Wg = (const float*)d_in[1];
    const float* bg = (const float*)d_in[2];
    const float* Wp = (const float*)d_in[3];
    const float* bp = (const float*)d_in[4];
    const float* Wa = (const float*)d_in[5];
    const float* ba = (const float*)d_in[6];
    float* out = (float*)d_out;

    cudaFuncSetAttribute(policy_kernel, cudaFuncAttributeMaxDynamicSharedMemorySize, SMEM_BYTES);
    policy_kernel<<<GRIDX, NTHR, SMEM_BYTES>>>(x, Wg, bg, Wp, bp, Wa, ba, out);
}